// round 4
// baseline (speedup 1.0000x reference)
#include <cuda_runtime.h>

#define NN 50000
#define EE 800000
#define FDIM 128

// ---------------- scratch (device globals; no allocation) ----------------
__device__ float g_xl[NN * FDIM];
__device__ float g_xr[NN * FDIM];
__device__ float g_h[NN * FDIM];
__device__ int g_counts[NN];
__device__ int g_rowptr[NN + 1];
__device__ int g_next[NN];
__device__ int g_src[EE];
__device__ int g_is64;

// ---------------- edge_index dtype detection (int32 vs int64) ----------------
// For int64 non-negative indices, every odd 32-bit word (high half) is 0.
// For int32, odd words are random node ids (zero w.p. 2e-5). Deterministic.
__global__ void k_detect(const unsigned int* __restrict__ w) {
    __shared__ int cnt;
    if (threadIdx.x == 0) cnt = 0;
    __syncthreads();
    int z = 0;
    for (int i = threadIdx.x; i < 1024; i += 256)
        if (w[2 * i + 1] == 0u) z++;
    atomicAdd(&cnt, z);
    __syncthreads();
    if (threadIdx.x == 0) g_is64 = (cnt > 512) ? 1 : 0;
}

__device__ __forceinline__ int load_idx(const void* ei, long pos) {
    return g_is64 ? (int)((const long long*)ei)[pos] : ((const int*)ei)[pos];
}

// ---------------- CSR build ----------------
__global__ void k_zero_counts() {
    int i = blockIdx.x * blockDim.x + threadIdx.x;
    if (i < NN) g_counts[i] = 0;
}

__global__ void k_hist(const void* __restrict__ ei) {
    int e = blockIdx.x * blockDim.x + threadIdx.x;
    if (e < EE) atomicAdd(&g_counts[load_idx(ei, (long)EE + e)], 1);
}

// single-block exclusive scan of g_counts -> g_rowptr, g_next
__global__ void k_scan() {
    __shared__ int warp_sums[32];
    __shared__ int chunk_off;
    int t = threadIdx.x;
    int lane = t & 31, wid = t >> 5;
    if (t == 0) chunk_off = 0;
    __syncthreads();
    for (int base = 0; base < NN; base += 1024) {
        int i = base + t;
        int v = (i < NN) ? g_counts[i] : 0;
        int incl = v;
#pragma unroll
        for (int o = 1; o < 32; o <<= 1) {
            int xx = __shfl_up_sync(0xffffffffu, incl, o);
            if (lane >= o) incl += xx;
        }
        if (lane == 31) warp_sums[wid] = incl;
        __syncthreads();
        if (wid == 0) {
            int ws = warp_sums[lane];
            int wincl = ws;
#pragma unroll
            for (int o = 1; o < 32; o <<= 1) {
                int xx = __shfl_up_sync(0xffffffffu, wincl, o);
                if (lane >= o) wincl += xx;
            }
            warp_sums[lane] = wincl - ws;  // exclusive warp offsets
        }
        __syncthreads();
        int excl = chunk_off + warp_sums[wid] + incl - v;
        if (i < NN) { g_rowptr[i] = excl; g_next[i] = excl; }
        __syncthreads();
        if (t == 1023) chunk_off = excl + v;
        __syncthreads();
    }
    if (t == 0) g_rowptr[NN] = chunk_off;
}

__global__ void k_scatter(const void* __restrict__ ei) {
    int e = blockIdx.x * blockDim.x + threadIdx.x;
    if (e < EE) {
        int dn = load_idx(ei, (long)EE + e);
        int sn = load_idx(ei, e);
        int pos = atomicAdd(&g_next[dn], 1);
        g_src[pos] = sn;
    }
}

// ---------------- dual GEMM: g_xl = A@W1, g_xr = A@W2  (M=NN, K=N=128) ----------------
// block: 128 rows x 256 cols (both outputs), 512 threads, 8x8 micro-tile,
// K chunked by 32 so static smem = 16KB (As) + 32KB (Ws) = 48KB exactly.
template <bool USE_H>
__global__ void __launch_bounds__(512, 1)
k_dual_gemm(const float* __restrict__ A_param,
            const float* __restrict__ W1, const float* __restrict__ W2) {
    const float* A = USE_H ? (const float*)g_h : A_param;
    __shared__ float As[32][128];   // As[k][row] (transposed chunk)
    __shared__ float Ws[32][256];   // Ws[k][col] (W1 | W2)
    int t = threadIdx.x;
    int row0 = blockIdx.x * 128;
    int rt = t >> 5, ct = t & 31;   // rt warp-uniform -> As reads broadcast

    float acc[8][8];
#pragma unroll
    for (int i = 0; i < 8; i++)
#pragma unroll
        for (int j = 0; j < 8; j++) acc[i][j] = 0.f;

    for (int kc = 0; kc < 128; kc += 32) {
        // load A chunk (coalesced), store transposed
#pragma unroll
        for (int i = 0; i < 2; i++) {
            int idx = t + i * 512;
            int r = idx >> 3, c4 = idx & 7;
            float4 v = make_float4(0.f, 0.f, 0.f, 0.f);
            int gr = row0 + r;
            if (gr < NN) v = *(const float4*)(A + (long)gr * FDIM + kc + c4 * 4);
            As[c4 * 4 + 0][r] = v.x;
            As[c4 * 4 + 1][r] = v.y;
            As[c4 * 4 + 2][r] = v.z;
            As[c4 * 4 + 3][r] = v.w;
        }
        // load W1|W2 chunk
#pragma unroll
        for (int i = 0; i < 4; i++) {
            int idx = t + i * 512;
            int k = idx >> 6, c4 = idx & 63;
            float4 v;
            if (c4 < 32) v = *(const float4*)(W1 + (kc + k) * FDIM + c4 * 4);
            else         v = *(const float4*)(W2 + (kc + k) * FDIM + (c4 - 32) * 4);
            *(float4*)(&Ws[k][c4 * 4]) = v;
        }
        __syncthreads();

#pragma unroll 8
        for (int kk = 0; kk < 32; kk++) {
            float4 a0 = *(const float4*)(&As[kk][rt * 8]);
            float4 a1 = *(const float4*)(&As[kk][rt * 8 + 4]);
            float4 w0 = *(const float4*)(&Ws[kk][ct * 4]);
            float4 w1 = *(const float4*)(&Ws[kk][ct * 4 + 128]);
            float a[8] = {a0.x, a0.y, a0.z, a0.w, a1.x, a1.y, a1.z, a1.w};
            float w[8] = {w0.x, w0.y, w0.z, w0.w, w1.x, w1.y, w1.z, w1.w};
#pragma unroll
            for (int i = 0; i < 8; i++)
#pragma unroll
                for (int j = 0; j < 8; j++) acc[i][j] += a[i] * w[j];
        }
        __syncthreads();
    }

#pragma unroll
    for (int i = 0; i < 8; i++) {
        int gr = row0 + rt * 8 + i;
        if (gr < NN) {
            *(float4*)(g_xl + (long)gr * FDIM + ct * 4) =
                make_float4(acc[i][0], acc[i][1], acc[i][2], acc[i][3]);
            *(float4*)(g_xr + (long)gr * FDIM + ct * 4) =
                make_float4(acc[i][4], acc[i][5], acc[i][6], acc[i][7]);
        }
    }
}

// ---------------- fused per-node attention (online softmax), warp per node ----------------
__device__ __forceinline__ float lrelu(float v) { return v > 0.f ? v : 0.2f * v; }

template <int H, bool OUT_H>
__global__ void k_aggregate(const float* __restrict__ att, const float* __restrict__ bias,
                            float* __restrict__ out_param) {
    float* out = OUT_H ? (float*)g_h : out_param;
    int gw = (blockIdx.x * blockDim.x + threadIdx.x) >> 5;
    int lane = threadIdx.x & 31;
    if (gw >= NN) return;
    int n = gw;

    float4 xrv = *(const float4*)(g_xr + (long)n * FDIM + lane * 4);
    float4 av  = *(const float4*)(att + lane * 4);
    float4 bv  = *(const float4*)(bias + lane * 4);

    float m = __int_as_float(0xff800000);  // -inf
    float d = 0.f;
    float4 acc = make_float4(0.f, 0.f, 0.f, 0.f);

    int start = g_rowptr[n], end = g_rowptr[n + 1];
    for (int j = start; j <= end; j++) {
        int s = (j < end) ? g_src[j] : n;  // final iteration = self loop
        float4 xlv = *(const float4*)(g_xl + (long)s * FDIM + lane * 4);
        float p = lrelu(xlv.x + xrv.x) * av.x
                + lrelu(xlv.y + xrv.y) * av.y
                + lrelu(xlv.z + xrv.z) * av.z
                + lrelu(xlv.w + xrv.w) * av.w;
#pragma unroll
        for (int o = 1; o < 32 / H; o <<= 1)
            p += __shfl_xor_sync(0xffffffffu, p, o);
        float mn = fmaxf(m, p);
        float sc = __expf(m - mn);   // exp(-inf)=0 on first edge
        float pe = __expf(p - mn);
        d = d * sc + pe;
        acc.x = acc.x * sc + pe * xlv.x;
        acc.y = acc.y * sc + pe * xlv.y;
        acc.z = acc.z * sc + pe * xlv.z;
        acc.w = acc.w * sc + pe * xlv.w;
        m = mn;
    }
    float inv = 1.f / d;
    float4 o = make_float4(acc.x * inv + bv.x, acc.y * inv + bv.y,
                           acc.z * inv + bv.z, acc.w * inv + bv.w);
    *(float4*)(out + (long)n * FDIM + lane * 4) = o;
}

// ---------------- launch: kernel launches ONLY ----------------
extern "C" void kernel_launch(void* const* d_in, const int* in_sizes, int n_in,
                              void* d_out, int out_size) {
    const float* x    = (const float*)d_in[0];
    const void*  ei   = d_in[1];
    // d_in[2] = edge_attr (unused)
    const float* Wl1  = (const float*)d_in[3];
    const float* Wr1  = (const float*)d_in[4];
    const float* att1 = (const float*)d_in[5];
    const float* b1   = (const float*)d_in[6];
    const float* Wl2  = (const float*)d_in[7];
    const float* Wr2  = (const float*)d_in[8];
    const float* att2 = (const float*)d_in[9];
    const float* b2   = (const float*)d_in[10];
    float* out = (float*)d_out;

    // dtype probe + CSR build (reused by both layers)
    k_detect<<<1, 256>>>((const unsigned int*)ei);
    k_zero_counts<<<(NN + 255) / 256, 256>>>();
    k_hist<<<(EE + 255) / 256, 256>>>(ei);
    k_scan<<<1, 1024>>>();
    k_scatter<<<(EE + 255) / 256, 256>>>(ei);

    int gemm_blocks = (NN + 127) / 128;
    int agg_blocks = (NN + 7) / 8;  // 8 warps / block

    // layer 1: 128 -> (2 heads x 64)
    k_dual_gemm<false><<<gemm_blocks, 512>>>(x, Wl1, Wr1);
    k_aggregate<2, true><<<agg_blocks, 256>>>(att1, b1, nullptr);

    // layer 2: 128 -> (1 head x 128)
    k_dual_gemm<true><<<gemm_blocks, 512>>>(nullptr, Wl2, Wr2);
    k_aggregate<1, false><<<agg_blocks, 256>>>(att2, b2, out);
}

// round 5
// speedup vs baseline: 1.0711x; 1.0711x over previous
#include <cuda_runtime.h>

#define NN 50000
#define EE 800000
#define FDIM 128
#define NBLK 49  // ceil(NN/1024)

// ---------------- scratch (device globals; no allocation) ----------------
__device__ float g_xl[NN * FDIM];
__device__ float g_xr[NN * FDIM];
__device__ float g_h[NN * FDIM];
__device__ int g_counts[NN];
__device__ int g_rowptr[NN + 1];
__device__ int g_next[NN];
__device__ int g_src[EE];
__device__ int g_is64;
__device__ int g_blksum[64];
__device__ int g_blkoff[64];

// ---------------- f32x2 packed-FMA helpers (SASS FFMA2; PTX-only path) ----------------
__device__ __forceinline__ unsigned long long pack2(float x, float y) {
    unsigned long long r;
    asm("mov.b64 %0, {%1, %2};" : "=l"(r) : "f"(x), "f"(y));
    return r;
}
__device__ __forceinline__ void fma2(unsigned long long& d, unsigned long long a,
                                     unsigned long long b) {
    asm("fma.rn.f32x2 %0, %1, %2, %0;" : "+l"(d) : "l"(a), "l"(b));
}
__device__ __forceinline__ float2 unpack2(unsigned long long v) {
    float2 f;
    asm("mov.b64 {%0, %1}, %2;" : "=f"(f.x), "=f"(f.y) : "l"(v));
    return f;
}

// ---------------- edge_index dtype detection (int32 vs int64) ----------------
__global__ void k_detect(const unsigned int* __restrict__ w) {
    __shared__ int cnt;
    if (threadIdx.x == 0) cnt = 0;
    __syncthreads();
    int z = 0;
    for (int i = threadIdx.x; i < 1024; i += 256)
        if (w[2 * i + 1] == 0u) z++;
    atomicAdd(&cnt, z);
    __syncthreads();
    if (threadIdx.x == 0) g_is64 = (cnt > 512) ? 1 : 0;
}

__device__ __forceinline__ int load_idx(const void* ei, long pos) {
    return g_is64 ? (int)((const long long*)ei)[pos] : ((const int*)ei)[pos];
}

// ---------------- CSR build ----------------
__global__ void k_zero_counts() {
    int i = blockIdx.x * blockDim.x + threadIdx.x;
    if (i < NN) g_counts[i] = 0;
}

__global__ void k_hist(const void* __restrict__ ei) {
    int e = blockIdx.x * blockDim.x + threadIdx.x;
    if (e < EE) atomicAdd(&g_counts[load_idx(ei, (long)EE + e)], 1);
}

// hierarchical scan: per-block exclusive scan + block sums
__global__ void k_scan_block() {
    __shared__ int wsum[32];
    int i = blockIdx.x * 1024 + threadIdx.x;
    int lane = threadIdx.x & 31, wid = threadIdx.x >> 5;
    int v = (i < NN) ? g_counts[i] : 0;
    int incl = v;
#pragma unroll
    for (int o = 1; o < 32; o <<= 1) {
        int xx = __shfl_up_sync(0xffffffffu, incl, o);
        if (lane >= o) incl += xx;
    }
    if (lane == 31) wsum[wid] = incl;
    __syncthreads();
    if (wid == 0) {
        int ws = wsum[lane];
        int wincl = ws;
#pragma unroll
        for (int o = 1; o < 32; o <<= 1) {
            int xx = __shfl_up_sync(0xffffffffu, wincl, o);
            if (lane >= o) wincl += xx;
        }
        wsum[lane] = wincl - ws;
    }
    __syncthreads();
    int excl = wsum[wid] + incl - v;
    if (i < NN) g_rowptr[i] = excl;
    if (threadIdx.x == 1023) g_blksum[blockIdx.x] = excl + v;
}

// single-warp scan of block sums (2 per lane)
__global__ void k_scan_tops() {
    int lane = threadIdx.x;
    int v0 = (2 * lane < NBLK) ? g_blksum[2 * lane] : 0;
    int v1 = (2 * lane + 1 < NBLK) ? g_blksum[2 * lane + 1] : 0;
    int s = v0 + v1;
    int incl = s;
#pragma unroll
    for (int o = 1; o < 32; o <<= 1) {
        int xx = __shfl_up_sync(0xffffffffu, incl, o);
        if (lane >= o) incl += xx;
    }
    int excl = incl - s;
    if (2 * lane < NBLK) g_blkoff[2 * lane] = excl;
    if (2 * lane + 1 < NBLK) g_blkoff[2 * lane + 1] = excl + v0;
    if (lane == 31) g_rowptr[NN] = incl;
}

__global__ void k_scan_add() {
    int i = blockIdx.x * 1024 + threadIdx.x;
    if (i < NN) {
        int r = g_rowptr[i] + g_blkoff[blockIdx.x];
        g_rowptr[i] = r;
        g_next[i] = r;
    }
}

__global__ void k_scatter(const void* __restrict__ ei) {
    int e = blockIdx.x * blockDim.x + threadIdx.x;
    if (e < EE) {
        int dn = load_idx(ei, (long)EE + e);
        int sn = load_idx(ei, e);
        int pos = atomicAdd(&g_next[dn], 1);
        g_src[pos] = sn;
    }
}

// ---------------- dual GEMM: g_xl = A@W1, g_xr = A@W2  (M=NN, K=N=128) ----------------
// 128x256 block tile, 512 threads, 8x8 micro-tile via f32x2 packed FMA.
template <bool USE_H>
__global__ void __launch_bounds__(512, 1)
k_dual_gemm(const float* __restrict__ A_param,
            const float* __restrict__ W1, const float* __restrict__ W2) {
    const float* A = USE_H ? (const float*)g_h : A_param;
    __shared__ float As[32][128];   // As[k][row] (transposed chunk)
    __shared__ float Ws[32][256];   // Ws[k][col] (W1 | W2)
    int t = threadIdx.x;
    int row0 = blockIdx.x * 128;
    int rt = t >> 5, ct = t & 31;   // rt warp-uniform -> As reads broadcast

    unsigned long long acc2[8][4];
#pragma unroll
    for (int i = 0; i < 8; i++)
#pragma unroll
        for (int j = 0; j < 4; j++) acc2[i][j] = 0ull;

    for (int kc = 0; kc < 128; kc += 32) {
#pragma unroll
        for (int i = 0; i < 2; i++) {
            int idx = t + i * 512;
            int r = idx >> 3, c4 = idx & 7;
            float4 v = make_float4(0.f, 0.f, 0.f, 0.f);
            int gr = row0 + r;
            if (gr < NN) v = *(const float4*)(A + (long)gr * FDIM + kc + c4 * 4);
            As[c4 * 4 + 0][r] = v.x;
            As[c4 * 4 + 1][r] = v.y;
            As[c4 * 4 + 2][r] = v.z;
            As[c4 * 4 + 3][r] = v.w;
        }
#pragma unroll
        for (int i = 0; i < 4; i++) {
            int idx = t + i * 512;
            int k = idx >> 6, c4 = idx & 63;
            float4 v;
            if (c4 < 32) v = *(const float4*)(W1 + (kc + k) * FDIM + c4 * 4);
            else         v = *(const float4*)(W2 + (kc + k) * FDIM + (c4 - 32) * 4);
            *(float4*)(&Ws[k][c4 * 4]) = v;
        }
        __syncthreads();

#pragma unroll 8
        for (int kk = 0; kk < 32; kk++) {
            float4 a0 = *(const float4*)(&As[kk][rt * 8]);
            float4 a1 = *(const float4*)(&As[kk][rt * 8 + 4]);
            float4 w0 = *(const float4*)(&Ws[kk][ct * 4]);
            float4 w1 = *(const float4*)(&Ws[kk][ct * 4 + 128]);
            unsigned long long wp[4];
            wp[0] = pack2(w0.x, w0.y);
            wp[1] = pack2(w0.z, w0.w);
            wp[2] = pack2(w1.x, w1.y);
            wp[3] = pack2(w1.z, w1.w);
            float a[8] = {a0.x, a0.y, a0.z, a0.w, a1.x, a1.y, a1.z, a1.w};
#pragma unroll
            for (int i = 0; i < 8; i++) {
                unsigned long long ap = pack2(a[i], a[i]);
#pragma unroll
                for (int j = 0; j < 4; j++) fma2(acc2[i][j], ap, wp[j]);
            }
        }
        __syncthreads();
    }

#pragma unroll
    for (int i = 0; i < 8; i++) {
        int gr = row0 + rt * 8 + i;
        if (gr < NN) {
            float2 p0 = unpack2(acc2[i][0]), p1 = unpack2(acc2[i][1]);
            float2 p2 = unpack2(acc2[i][2]), p3 = unpack2(acc2[i][3]);
            *(float4*)(g_xl + (long)gr * FDIM + ct * 4) =
                make_float4(p0.x, p0.y, p1.x, p1.y);
            *(float4*)(g_xr + (long)gr * FDIM + ct * 4) =
                make_float4(p2.x, p2.y, p3.x, p3.y);
        }
    }
}

// ---------------- fused per-node attention (online softmax), warp per node ----------------
__device__ __forceinline__ float lrelu(float v) { return v > 0.f ? v : 0.2f * v; }

template <int H, bool OUT_H>
__global__ void k_aggregate(const float* __restrict__ att, const float* __restrict__ bias,
                            float* __restrict__ out_param) {
    float* out = OUT_H ? (float*)g_h : out_param;
    int gw = (blockIdx.x * blockDim.x + threadIdx.x) >> 5;
    int lane = threadIdx.x & 31;
    if (gw >= NN) return;
    int n = gw;

    float4 xrv = *(const float4*)(g_xr + (long)n * FDIM + lane * 4);
    float4 av  = *(const float4*)(att + lane * 4);
    float4 bv  = *(const float4*)(bias + lane * 4);

    float m = __int_as_float(0xff800000);
    float d = 0.f;
    float4 acc = make_float4(0.f, 0.f, 0.f, 0.f);

    int start = g_rowptr[n], end = g_rowptr[n + 1];
    for (int j = start; j <= end; j++) {
        int s = (j < end) ? g_src[j] : n;  // final iteration = self loop
        float4 xlv = *(const float4*)(g_xl + (long)s * FDIM + lane * 4);
        float p = lrelu(xlv.x + xrv.x) * av.x
                + lrelu(xlv.y + xrv.y) * av.y
                + lrelu(xlv.z + xrv.z) * av.z
                + lrelu(xlv.w + xrv.w) * av.w;
#pragma unroll
        for (int o = 1; o < 32 / H; o <<= 1)
            p += __shfl_xor_sync(0xffffffffu, p, o);
        float mn = fmaxf(m, p);
        float sc = __expf(m - mn);
        float pe = __expf(p - mn);
        d = d * sc + pe;
        acc.x = acc.x * sc + pe * xlv.x;
        acc.y = acc.y * sc + pe * xlv.y;
        acc.z = acc.z * sc + pe * xlv.z;
        acc.w = acc.w * sc + pe * xlv.w;
        m = mn;
    }
    float inv = 1.f / d;
    float4 o = make_float4(acc.x * inv + bv.x, acc.y * inv + bv.y,
                           acc.z * inv + bv.z, acc.w * inv + bv.w);
    *(float4*)(out + (long)n * FDIM + lane * 4) = o;
}

// ---------------- launch: kernel launches ONLY ----------------
extern "C" void kernel_launch(void* const* d_in, const int* in_sizes, int n_in,
                              void* d_out, int out_size) {
    const float* x    = (const float*)d_in[0];
    const void*  ei   = d_in[1];
    const float* Wl1  = (const float*)d_in[3];
    const float* Wr1  = (const float*)d_in[4];
    const float* att1 = (const float*)d_in[5];
    const float* b1   = (const float*)d_in[6];
    const float* Wl2  = (const float*)d_in[7];
    const float* Wr2  = (const float*)d_in[8];
    const float* att2 = (const float*)d_in[9];
    const float* b2   = (const float*)d_in[10];
    float* out = (float*)d_out;

    k_detect<<<1, 256>>>((const unsigned int*)ei);
    k_zero_counts<<<(NN + 255) / 256, 256>>>();
    k_hist<<<(EE + 255) / 256, 256>>>(ei);
    k_scan_block<<<NBLK, 1024>>>();
    k_scan_tops<<<1, 32>>>();
    k_scan_add<<<NBLK, 1024>>>();
    k_scatter<<<(EE + 255) / 256, 256>>>(ei);

    int gemm_blocks = (NN + 127) / 128;
    int agg_blocks = (NN + 7) / 8;

    // layer 1: 128 -> (2 heads x 64)
    k_dual_gemm<false><<<gemm_blocks, 512>>>(x, Wl1, Wr1);
    k_aggregate<2, true><<<agg_blocks, 256>>>(att1, b1, nullptr);

    // layer 2: 128 -> (1 head x 128)
    k_dual_gemm<true><<<gemm_blocks, 512>>>(nullptr, Wl2, Wr2);
    k_aggregate<1, false><<<agg_blocks, 256>>>(att2, b2, out);
}

// round 6
// speedup vs baseline: 1.1255x; 1.0509x over previous
#include <cuda_runtime.h>

#define NN 50000
#define EE 800000
#define FDIM 128
#define NBLK 49  // ceil(NN/1024)

// ---------------- scratch (device globals; no allocation) ----------------
__device__ float g_xl[NN * FDIM];
__device__ float g_xr[NN * FDIM];
__device__ float g_h[NN * FDIM];
__device__ int g_counts[NN];
__device__ int g_rowptr[NN + 1];
__device__ int g_next[NN];
__device__ int g_src[EE];
__device__ int g_is64;
__device__ int g_blksum[64];
__device__ int g_blkoff[64];

// ---------------- f32x2 packed-FMA helpers (SASS FFMA2; PTX-only path) ----------------
__device__ __forceinline__ unsigned long long pack2(float x, float y) {
    unsigned long long r;
    asm("mov.b64 %0, {%1, %2};" : "=l"(r) : "f"(x), "f"(y));
    return r;
}
__device__ __forceinline__ void fma2(unsigned long long& d, unsigned long long a,
                                     unsigned long long b) {
    asm("fma.rn.f32x2 %0, %1, %2, %0;" : "+l"(d) : "l"(a), "l"(b));
}
__device__ __forceinline__ float2 unpack2(unsigned long long v) {
    float2 f;
    asm("mov.b64 {%0, %1}, %2;" : "=f"(f.x), "=f"(f.y) : "l"(v));
    return f;
}

// ---------------- detect dtype (int32 vs int64) + zero counts, one launch ----------------
__global__ void k_detect_zero(const unsigned int* __restrict__ w) {
    int i = blockIdx.x * 256 + threadIdx.x;
    if (i < NN) g_counts[i] = 0;
    if (blockIdx.x == 0) {
        __shared__ int cnt;
        if (threadIdx.x == 0) cnt = 0;
        __syncthreads();
        int z = 0;
        for (int k = threadIdx.x; k < 1024; k += 256)
            if (w[2 * k + 1] == 0u) z++;
        atomicAdd(&cnt, z);
        __syncthreads();
        if (threadIdx.x == 0) g_is64 = (cnt > 512) ? 1 : 0;
    }
}

__device__ __forceinline__ int load_idx(const void* ei, long pos) {
    return g_is64 ? (int)((const long long*)ei)[pos] : ((const int*)ei)[pos];
}

// ---------------- CSR build ----------------
__global__ void k_hist(const void* __restrict__ ei) {
    int e = blockIdx.x * blockDim.x + threadIdx.x;
    if (e < EE) atomicAdd(&g_counts[load_idx(ei, (long)EE + e)], 1);
}

__global__ void k_scan_block() {
    __shared__ int wsum[32];
    int i = blockIdx.x * 1024 + threadIdx.x;
    int lane = threadIdx.x & 31, wid = threadIdx.x >> 5;
    int v = (i < NN) ? g_counts[i] : 0;
    int incl = v;
#pragma unroll
    for (int o = 1; o < 32; o <<= 1) {
        int xx = __shfl_up_sync(0xffffffffu, incl, o);
        if (lane >= o) incl += xx;
    }
    if (lane == 31) wsum[wid] = incl;
    __syncthreads();
    if (wid == 0) {
        int ws = wsum[lane];
        int wincl = ws;
#pragma unroll
        for (int o = 1; o < 32; o <<= 1) {
            int xx = __shfl_up_sync(0xffffffffu, wincl, o);
            if (lane >= o) wincl += xx;
        }
        wsum[lane] = wincl - ws;
    }
    __syncthreads();
    int excl = wsum[wid] + incl - v;
    if (i < NN) g_rowptr[i] = excl;
    if (threadIdx.x == 1023) g_blksum[blockIdx.x] = excl + v;
}

__global__ void k_scan_tops() {
    int lane = threadIdx.x;
    int v0 = (2 * lane < NBLK) ? g_blksum[2 * lane] : 0;
    int v1 = (2 * lane + 1 < NBLK) ? g_blksum[2 * lane + 1] : 0;
    int s = v0 + v1;
    int incl = s;
#pragma unroll
    for (int o = 1; o < 32; o <<= 1) {
        int xx = __shfl_up_sync(0xffffffffu, incl, o);
        if (lane >= o) incl += xx;
    }
    int excl = incl - s;
    if (2 * lane < NBLK) g_blkoff[2 * lane] = excl;
    if (2 * lane + 1 < NBLK) g_blkoff[2 * lane + 1] = excl + v0;
    if (lane == 31) g_rowptr[NN] = incl;
}

__global__ void k_scan_add() {
    int i = blockIdx.x * 1024 + threadIdx.x;
    if (i < NN) {
        int r = g_rowptr[i] + g_blkoff[blockIdx.x];
        g_rowptr[i] = r;
        g_next[i] = r;
    }
}

__global__ void k_scatter(const void* __restrict__ ei) {
    int e = blockIdx.x * blockDim.x + threadIdx.x;
    if (e < EE) {
        int dn = load_idx(ei, (long)EE + e);
        int sn = load_idx(ei, e);
        int pos = atomicAdd(&g_next[dn], 1);
        g_src[pos] = sn;
    }
}

// ---------------- dual GEMM: g_xl = A@W1, g_xr = A@W2  (M=NN, K=N=128) ----------------
// 128x256 block tile, 512 threads, 8x8 micro-tile via f32x2 packed FMA,
// software-pipelined global->smem loads.
template <bool USE_H>
__global__ void __launch_bounds__(512, 1)
k_dual_gemm(const float* __restrict__ A_param,
            const float* __restrict__ W1, const float* __restrict__ W2) {
    const float* A = USE_H ? (const float*)g_h : A_param;
    __shared__ float As[32][128];   // As[k][row] (transposed chunk)
    __shared__ float Ws[32][256];   // Ws[k][col] (W1 | W2)
    int t = threadIdx.x;
    int row0 = blockIdx.x * 128;
    int rt = t >> 5, ct = t & 31;   // rt warp-uniform -> As reads broadcast

    // load coordinates (constant per thread)
    int ar0 = t >> 3, ac0 = t & 7;                 // i=0
    int ar1 = (t + 512) >> 3, ac1 = (t + 512) & 7; // i=1
    int gr0 = row0 + ar0, gr1 = row0 + ar1;

    unsigned long long acc2[8][4];
#pragma unroll
    for (int i = 0; i < 8; i++)
#pragma unroll
        for (int j = 0; j < 4; j++) acc2[i][j] = 0ull;

    float4 aT[2], wT[4];
    // prologue load: chunk kc=0
    aT[0] = (gr0 < NN) ? *(const float4*)(A + (long)gr0 * FDIM + ac0 * 4)
                       : make_float4(0.f, 0.f, 0.f, 0.f);
    aT[1] = (gr1 < NN) ? *(const float4*)(A + (long)gr1 * FDIM + ac1 * 4)
                       : make_float4(0.f, 0.f, 0.f, 0.f);
#pragma unroll
    for (int i = 0; i < 4; i++) {
        int idx = t + i * 512;
        int k = idx >> 6, c4 = idx & 63;
        wT[i] = (c4 < 32) ? *(const float4*)(W1 + k * FDIM + c4 * 4)
                          : *(const float4*)(W2 + k * FDIM + (c4 - 32) * 4);
    }

    for (int kc = 0; kc < 128; kc += 32) {
        // store staged chunk to smem
        As[ac0 * 4 + 0][ar0] = aT[0].x;
        As[ac0 * 4 + 1][ar0] = aT[0].y;
        As[ac0 * 4 + 2][ar0] = aT[0].z;
        As[ac0 * 4 + 3][ar0] = aT[0].w;
        As[ac1 * 4 + 0][ar1] = aT[1].x;
        As[ac1 * 4 + 1][ar1] = aT[1].y;
        As[ac1 * 4 + 2][ar1] = aT[1].z;
        As[ac1 * 4 + 3][ar1] = aT[1].w;
#pragma unroll
        for (int i = 0; i < 4; i++) {
            int idx = t + i * 512;
            int k = idx >> 6, c4 = idx & 63;
            *(float4*)(&Ws[k][c4 * 4]) = wT[i];
        }
        __syncthreads();

        // prefetch next chunk while computing
        int kn = kc + 32;
        if (kn < 128) {
            aT[0] = (gr0 < NN) ? *(const float4*)(A + (long)gr0 * FDIM + kn + ac0 * 4)
                               : make_float4(0.f, 0.f, 0.f, 0.f);
            aT[1] = (gr1 < NN) ? *(const float4*)(A + (long)gr1 * FDIM + kn + ac1 * 4)
                               : make_float4(0.f, 0.f, 0.f, 0.f);
#pragma unroll
            for (int i = 0; i < 4; i++) {
                int idx = t + i * 512;
                int k = idx >> 6, c4 = idx & 63;
                wT[i] = (c4 < 32) ? *(const float4*)(W1 + (kn + k) * FDIM + c4 * 4)
                                  : *(const float4*)(W2 + (kn + k) * FDIM + (c4 - 32) * 4);
            }
        }

#pragma unroll 4
        for (int kk = 0; kk < 32; kk++) {
            float4 a0 = *(const float4*)(&As[kk][rt * 8]);
            float4 a1 = *(const float4*)(&As[kk][rt * 8 + 4]);
            // W pairs come straight from LDS.128 as packed f32x2 operands
            ulonglong2 w01 = *(const ulonglong2*)(&Ws[kk][ct * 4]);
            ulonglong2 w23 = *(const ulonglong2*)(&Ws[kk][ct * 4 + 128]);
            unsigned long long wp0 = w01.x, wp1 = w01.y, wp2 = w23.x, wp3 = w23.y;
            float a[8] = {a0.x, a0.y, a0.z, a0.w, a1.x, a1.y, a1.z, a1.w};
#pragma unroll
            for (int i = 0; i < 8; i++) {
                unsigned long long ap = pack2(a[i], a[i]);
                fma2(acc2[i][0], ap, wp0);
                fma2(acc2[i][1], ap, wp1);
                fma2(acc2[i][2], ap, wp2);
                fma2(acc2[i][3], ap, wp3);
            }
        }
        __syncthreads();
    }

#pragma unroll
    for (int i = 0; i < 8; i++) {
        int gr = row0 + rt * 8 + i;
        if (gr < NN) {
            float2 p0 = unpack2(acc2[i][0]), p1 = unpack2(acc2[i][1]);
            float2 p2 = unpack2(acc2[i][2]), p3 = unpack2(acc2[i][3]);
            *(float4*)(g_xl + (long)gr * FDIM + ct * 4) =
                make_float4(p0.x, p0.y, p1.x, p1.y);
            *(float4*)(g_xr + (long)gr * FDIM + ct * 4) =
                make_float4(p2.x, p2.y, p3.x, p3.y);
        }
    }
}

// ---------------- fused per-node attention (online softmax), warp per node ----------------
__device__ __forceinline__ float lrelu(float v) { return v > 0.f ? v : 0.2f * v; }

template <int H, bool OUT_H>
__global__ void k_aggregate(const float* __restrict__ att, const float* __restrict__ bias,
                            float* __restrict__ out_param) {
    float* out = OUT_H ? (float*)g_h : out_param;
    int gw = (blockIdx.x * blockDim.x + threadIdx.x) >> 5;
    int lane = threadIdx.x & 31;
    if (gw >= NN) return;
    int n = gw;

    float4 xrv = *(const float4*)(g_xr + (long)n * FDIM + lane * 4);
    float4 av  = *(const float4*)(att + lane * 4);
    float4 bv  = *(const float4*)(bias + lane * 4);

    // self-loop first: bootstraps m/d/acc, no -inf handling
    float4 xlv = *(const float4*)(g_xl + (long)n * FDIM + lane * 4);
    float p = lrelu(xlv.x + xrv.x) * av.x
            + lrelu(xlv.y + xrv.y) * av.y
            + lrelu(xlv.z + xrv.z) * av.z
            + lrelu(xlv.w + xrv.w) * av.w;
#pragma unroll
    for (int o = 1; o < 32 / H; o <<= 1)
        p += __shfl_xor_sync(0xffffffffu, p, o);
    float m = p;
    float d = 1.f;
    float4 acc = xlv;

    int start = g_rowptr[n], end = g_rowptr[n + 1];
    for (int j = start; j < end; j++) {
        int s = g_src[j];
        xlv = *(const float4*)(g_xl + (long)s * FDIM + lane * 4);
        p = lrelu(xlv.x + xrv.x) * av.x
          + lrelu(xlv.y + xrv.y) * av.y
          + lrelu(xlv.z + xrv.z) * av.z
          + lrelu(xlv.w + xrv.w) * av.w;
#pragma unroll
        for (int o = 1; o < 32 / H; o <<= 1)
            p += __shfl_xor_sync(0xffffffffu, p, o);
        if (p > m) {           // new max: rescale (rare after first edges)
            float sc = __expf(m - p);
            d = fmaf(d, sc, 1.f);
            acc.x = fmaf(acc.x, sc, xlv.x);
            acc.y = fmaf(acc.y, sc, xlv.y);
            acc.z = fmaf(acc.z, sc, xlv.z);
            acc.w = fmaf(acc.w, sc, xlv.w);
            m = p;
        } else {               // common path: one exp, no rescale
            float pe = __expf(p - m);
            d += pe;
            acc.x = fmaf(pe, xlv.x, acc.x);
            acc.y = fmaf(pe, xlv.y, acc.y);
            acc.z = fmaf(pe, xlv.z, acc.z);
            acc.w = fmaf(pe, xlv.w, acc.w);
        }
    }
    float inv = 1.f / d;
    float4 o = make_float4(fmaf(acc.x, inv, bv.x), fmaf(acc.y, inv, bv.y),
                           fmaf(acc.z, inv, bv.z), fmaf(acc.w, inv, bv.w));
    *(float4*)(out + (long)n * FDIM + lane * 4) = o;
}

// ---------------- launch: kernel launches ONLY ----------------
extern "C" void kernel_launch(void* const* d_in, const int* in_sizes, int n_in,
                              void* d_out, int out_size) {
    const float* x    = (const float*)d_in[0];
    const void*  ei   = d_in[1];
    const float* Wl1  = (const float*)d_in[3];
    const float* Wr1  = (const float*)d_in[4];
    const float* att1 = (const float*)d_in[5];
    const float* b1   = (const float*)d_in[6];
    const float* Wl2  = (const float*)d_in[7];
    const float* Wr2  = (const float*)d_in[8];
    const float* att2 = (const float*)d_in[9];
    const float* b2   = (const float*)d_in[10];
    float* out = (float*)d_out;

    int gemm_blocks = (NN + 127) / 128;
    int agg_blocks = (NN + 7) / 8;

    // order chosen so our launch #3 (ncu capture slot) = k_dual_gemm<false>
    k_detect_zero<<<(NN + 255) / 256, 256>>>((const unsigned int*)ei);  // 0
    k_hist<<<(EE + 255) / 256, 256>>>(ei);                              // 1
    k_scan_block<<<NBLK, 1024>>>();                                     // 2
    k_dual_gemm<false><<<gemm_blocks, 512>>>(x, Wl1, Wr1);              // 3 (profiled)
    k_scan_tops<<<1, 32>>>();                                           // 4
    k_scan_add<<<NBLK, 1024>>>();                                       // 5
    k_scatter<<<(EE + 255) / 256, 256>>>(ei);                           // 6
    k_aggregate<2, true><<<agg_blocks, 256>>>(att1, b1, nullptr);       // 7
    k_dual_gemm<true><<<gemm_blocks, 512>>>(nullptr, Wl2, Wr2);         // 8
    k_aggregate<1, false><<<agg_blocks, 256>>>(att2, b2, out);          // 9
}